// round 3
// baseline (speedup 1.0000x reference)
#include <cuda_runtime.h>
#include <math.h>

#define NB 16
#define NN 48
#define HID 64
#define MSG 64
#define EDGE 16
#define NL 128
#define TGT 128
#define NE (NB*NN*NN)    // 36864 edges
#define NNODE (NB*NN)    // 768 nodes

// -------- device scratch (static; no allocation) --------
__device__ float2 d_SP[3*NL*MSG];    // [sel][c][m] -> (S_cut, S64 - S_cut)
__device__ float2 d_Bp[3*MSG];       // [sel][m]    -> (B_cut, B64 - B_cut)
__device__ float2 d_T[3*NL*192];     // folded Wih·SP: [sel][c][gc] -> (t0, t1)
__device__ float2 d_v[3*192];        // folded Wih·Bp: [sel][gc]
__device__ float  d_whht[HID*3*HID]; // transposed gru_whh: [k][gate*64+c]
__device__ unsigned d_w1t[NL*NL];    // msg_w1 transposed [n][k], tf32 bits
__device__ unsigned d_w0t[NL*EDGE];  // msg_w0 transposed [n][k], tf32 bits
__device__ float d_r2[NE*NL];        // relu2 activations per edge [e'][c]
__device__ float d_hf[NNODE*HID];    // h_first
__device__ float d_hA[NNODE*HID];
__device__ float d_hB[NNODE*HID];
__device__ float d_mask[NNODE];
__device__ float d_tmp[NNODE*TGT];

__device__ __forceinline__ unsigned f2tf32(float f) {
    unsigned u;
    asm("cvt.rna.tf32.f32 %0, %1;" : "=r"(u) : "f"(f));
    return u;
}

#define MMA_TF32(c0,c1,c2,c3,a0,a1,a2,a3,b0,b1) \
  asm volatile("mma.sync.aligned.m16n8k8.row.col.f32.tf32.tf32.f32 " \
    "{%0,%1,%2,%3},{%4,%5,%6,%7},{%8,%9},{%0,%1,%2,%3};" \
    : "+f"(c0),"+f"(c1),"+f"(c2),"+f"(c3) \
    : "r"(a0),"r"(a1),"r"(a2),"r"(a3),"r"(b0),"r"(b1))

// -------- prep: prefix-sum weight tables --------
__global__ void prep_kernel(const float* __restrict__ w2, const float* __restrict__ b2) {
    int c = blockIdx.x;   // 0..127
    int m = threadIdx.x;  // 0..63
    const float* p = w2 + c*4096 + m*64;
    float acc = 0.f, s16 = 0.f, s32 = 0.f, s48 = 0.f;
    #pragma unroll
    for (int h = 0; h < 64; ++h) {
        acc += p[h];
        if (h == 15) s16 = acc;
        if (h == 31) s32 = acc;
        if (h == 47) s48 = acc;
    }
    d_SP[0*8192 + c*64 + m] = make_float2(s16, acc - s16);
    d_SP[1*8192 + c*64 + m] = make_float2(s32, acc - s32);
    d_SP[2*8192 + c*64 + m] = make_float2(s48, acc - s48);
    if (c == 0) {
        const float* q = b2 + m*64;
        float a = 0.f, t16 = 0.f, t32 = 0.f, t48 = 0.f;
        for (int h = 0; h < 64; ++h) {
            a += q[h];
            if (h == 15) t16 = a;
            if (h == 31) t32 = a;
            if (h == 47) t48 = a;
        }
        d_Bp[0*64+m] = make_float2(t16, a - t16);
        d_Bp[1*64+m] = make_float2(t32, a - t32);
        d_Bp[2*64+m] = make_float2(t48, a - t48);
    }
}

// -------- prep: fold Wih into SP tables: T[sel][c][gc] --------
__global__ void prep_T_kernel(const float* __restrict__ wih) {
    int sc = blockIdx.x;      // sel*128 + c, 0..383
    int sel = sc >> 7, c = sc & 127;
    int gc = threadIdx.x;     // 0..191
    __shared__ float2 sp[64];
    if (gc < 64) sp[gc] = d_SP[sel*8192 + c*64 + gc];
    __syncthreads();
    float t0 = 0.f, t1 = 0.f;
    const float* wr = wih + gc*64;
    #pragma unroll 8
    for (int m = 0; m < 64; ++m) {
        float w = wr[m];
        t0 += w*sp[m].x; t1 += w*sp[m].y;
    }
    d_T[sc*192 + gc] = make_float2(t0, t1);
}

__global__ void prep_v_kernel(const float* __restrict__ wih) {
    int sel = blockIdx.x; int gc = threadIdx.x;
    float v0 = 0.f, v1 = 0.f;
    for (int m = 0; m < 64; ++m) {
        float w = wih[gc*64+m];
        float2 bp = d_Bp[sel*64+m];
        v0 += w*bp.x; v1 += w*bp.y;
    }
    d_v[sel*192+gc] = make_float2(v0, v1);
}

// -------- prep: transpose GRU whh + msg weights (tf32) --------
__global__ void prep_gru_kernel(const float* __restrict__ whh) {
    int k = blockIdx.x;       // 0..63
    int t = threadIdx.x;      // 0..191
    d_whht[k*192 + t] = whh[t*64 + k];
}

__global__ void prep_w1t_kernel(const float* __restrict__ w1) {
    int idx = blockIdx.x*256 + threadIdx.x;  // n*128+k
    int n = idx >> 7, k = idx & 127;
    d_w1t[idx] = f2tf32(w1[k*128 + n]);
}

__global__ void prep_w0t_kernel(const float* __restrict__ w0) {
    int idx = blockIdx.x*256 + threadIdx.x;  // n*16+k
    int n = idx >> 4, k = idx & 15;
    d_w0t[idx] = f2tf32(w0[k*128 + n]);
}

// -------- init: h_first + node mask --------
__global__ void init_kernel(const float* __restrict__ h0) {
    int node = blockIdx.x; int c = threadIdx.x; // 64 threads
    float v = (c < 32) ? h0[node*32 + c] : 0.f;
    d_hf[node*64 + c] = v;
    float s = (c < 32) ? v : 0.f;
    #pragma unroll
    for (int off = 16; off > 0; off >>= 1) s += __shfl_down_sync(0xffffffffu, s, off);
    if (c == 0) d_mask[node] = (s > 0.f) ? 1.f : 0.f;
}

// -------- edge MLP via tf32 tensor cores: 128 rows per CTA --------
// smem floats: W1U 128*132 | X1U 128*132 | ESU 128*20 | W0U 128*20 | B0S 128 | B1S 128
#define RELU2_SMEM ((128*132*2 + 128*20*2 + 256)*4)
__global__ void __launch_bounds__(256) relu2_kernel(const float* __restrict__ e,
        const float* __restrict__ b0, const float* __restrict__ b1) {
    extern __shared__ char smem_raw[];
    unsigned* W1U = (unsigned*)smem_raw;
    unsigned* X1U = W1U + 128*132;
    unsigned* ESU = X1U + 128*132;
    unsigned* W0U = ESU + 128*20;
    float* B0S = (float*)(W0U + 128*20);
    float* B1S = B0S + 128;
    int t = threadIdx.x;
    int row0 = blockIdx.x * 128;

    // stage
    for (int idx = t; idx < 16384; idx += 256) {
        int n = idx >> 7, k = idx & 127;
        W1U[n*132 + k] = d_w1t[idx];
    }
    for (int idx = t; idx < 2048; idx += 256) {
        int r = idx >> 4, k = idx & 15;
        ESU[r*20 + k] = f2tf32(e[row0*16 + idx]);
        W0U[r*20 + k] = d_w0t[idx];       // r here = n
    }
    if (t < 128) { B0S[t] = b0[t]; B1S[t] = b1[t]; }
    __syncthreads();

    int lane = t & 31, warp = t >> 5;
    int rbase = warp * 16;
    int qrow = lane >> 2, qcol = lane & 3;

    float acc[16][4];
    // ---- layer 1: 16 -> 128 (relu) via mma ----
    #pragma unroll
    for (int nt = 0; nt < 16; ++nt) {
        float bv0 = B0S[nt*8 + 2*qcol], bv1 = B0S[nt*8 + 2*qcol + 1];
        acc[nt][0] = bv0; acc[nt][1] = bv1; acc[nt][2] = bv0; acc[nt][3] = bv1;
    }
    #pragma unroll
    for (int kt = 0; kt < 2; ++kt) {
        unsigned a0 = ESU[(rbase+qrow  )*20 + kt*8 + qcol];
        unsigned a1 = ESU[(rbase+qrow+8)*20 + kt*8 + qcol];
        unsigned a2 = ESU[(rbase+qrow  )*20 + kt*8 + 4 + qcol];
        unsigned a3 = ESU[(rbase+qrow+8)*20 + kt*8 + 4 + qcol];
        #pragma unroll
        for (int nt = 0; nt < 16; ++nt) {
            unsigned bb0 = W0U[(nt*8+qrow)*20 + kt*8 + qcol];
            unsigned bb1 = W0U[(nt*8+qrow)*20 + kt*8 + 4 + qcol];
            MMA_TF32(acc[nt][0],acc[nt][1],acc[nt][2],acc[nt][3],a0,a1,a2,a3,bb0,bb1);
        }
    }
    #pragma unroll
    for (int nt = 0; nt < 16; ++nt) {
        X1U[(rbase+qrow  )*132 + nt*8 + 2*qcol    ] = f2tf32(fmaxf(acc[nt][0], 0.f));
        X1U[(rbase+qrow  )*132 + nt*8 + 2*qcol + 1] = f2tf32(fmaxf(acc[nt][1], 0.f));
        X1U[(rbase+qrow+8)*132 + nt*8 + 2*qcol    ] = f2tf32(fmaxf(acc[nt][2], 0.f));
        X1U[(rbase+qrow+8)*132 + nt*8 + 2*qcol + 1] = f2tf32(fmaxf(acc[nt][3], 0.f));
    }
    __syncthreads();

    // ---- layer 2: 128 -> 128 (relu) via mma ----
    #pragma unroll
    for (int nt = 0; nt < 16; ++nt) {
        float bv0 = B1S[nt*8 + 2*qcol], bv1 = B1S[nt*8 + 2*qcol + 1];
        acc[nt][0] = bv0; acc[nt][1] = bv1; acc[nt][2] = bv0; acc[nt][3] = bv1;
    }
    #pragma unroll
    for (int kt = 0; kt < 16; ++kt) {
        unsigned a0 = X1U[(rbase+qrow  )*132 + kt*8 + qcol];
        unsigned a1 = X1U[(rbase+qrow+8)*132 + kt*8 + qcol];
        unsigned a2 = X1U[(rbase+qrow  )*132 + kt*8 + 4 + qcol];
        unsigned a3 = X1U[(rbase+qrow+8)*132 + kt*8 + 4 + qcol];
        #pragma unroll
        for (int nt = 0; nt < 16; ++nt) {
            unsigned bb0 = W1U[(nt*8+qrow)*132 + kt*8 + qcol];
            unsigned bb1 = W1U[(nt*8+qrow)*132 + kt*8 + 4 + qcol];
            MMA_TF32(acc[nt][0],acc[nt][1],acc[nt][2],acc[nt][3],a0,a1,a2,a3,bb0,bb1);
        }
    }
    __syncthreads();  // all warps done reading X1U

    // repack (relu) into X1 as fp32, then coalesced store
    float* X1F = (float*)X1U;
    #pragma unroll
    for (int nt = 0; nt < 16; ++nt) {
        X1F[(rbase+qrow  )*132 + nt*8 + 2*qcol    ] = fmaxf(acc[nt][0], 0.f);
        X1F[(rbase+qrow  )*132 + nt*8 + 2*qcol + 1] = fmaxf(acc[nt][1], 0.f);
        X1F[(rbase+qrow+8)*132 + nt*8 + 2*qcol    ] = fmaxf(acc[nt][2], 0.f);
        X1F[(rbase+qrow+8)*132 + nt*8 + 2*qcol + 1] = fmaxf(acc[nt][3], 0.f);
    }
    __syncthreads();
    for (int idx = t; idx < 4096; idx += 256) {
        int r = idx >> 5, c4 = idx & 31;
        float4 v = *(const float4*)&X1F[r*132 + c4*4];
        *(float4*)&d_r2[(row0+r)*128 + c4*4] = v;
    }
}

// -------- fused message-agg + GRU layer; 4 batches x one j per CTA --------
__global__ void __launch_bounds__(192) layer_kernel(int inbuf, int outbuf,
        const float* __restrict__ g,
        const float* __restrict__ bih, const float* __restrict__ bhh) {
    const float* h_in  = (inbuf  == 0) ? d_hf : ((inbuf  == 1) ? d_hA : d_hB);
    float*       h_out = (outbuf == 1) ? d_hA : d_hB;
    int j = blockIdx.x; int b0 = blockIdx.y * 4;
    int t = threadIdx.x;
    int k0 = (4*j)/3;
    int a64 = (64*j) % 48;            // in {0,16,32}
    int sel = (48 - a64)/16 - 1;      // 48->2, 32->1, 16->0

    __shared__ float a_s[4][48][2];
    __shared__ float hold[4][64];
    __shared__ float4 P0v[128];
    __shared__ float4 P1v[128];
    __shared__ float Qs[4][2];
    __shared__ float gis[4][192];
    __shared__ float ghs[4][192];

    // Phase A: gather g*h terms + own-node hidden
    for (int idx = t; idx < 384; idx += 192) {
        int bb = idx / 96, r = idx % 96, i = r >> 1, s = r & 1;
        int bi = (b0+bb)*48 + i;
        a_s[bb][i][s] = __ldg(&g[bi*48 + j]) * h_in[bi*64 + k0 + s];
    }
    for (int idx = t; idx < 256; idx += 192) {
        int bb = idx >> 6, c = idx & 63;
        hold[bb][c] = h_in[((b0+bb)*48 + j)*64 + c];
    }
    __syncthreads();

    // Phase B (threads 0-127): P_s[bb][c];  (threads 128-191): gh = Whh.hold + bhh
    if (t < 128) {
        int c = t;
        float p0[4] = {0,0,0,0}, p1[4] = {0,0,0,0};
        const float* bp[4];
        #pragma unroll
        for (int bb = 0; bb < 4; ++bb)
            bp[bb] = d_r2 + (size_t)((b0+bb)*48)*6144 + j*128 + c;
        #pragma unroll 4
        for (int i = 0; i < 48; ++i) {
            #pragma unroll
            for (int bb = 0; bb < 4; ++bb) {
                float r2v = __ldg(bp[bb] + i*6144);
                p0[bb] += a_s[bb][i][0]*r2v;
                p1[bb] += a_s[bb][i][1]*r2v;
            }
        }
        P0v[c] = make_float4(p0[0], p0[1], p0[2], p0[3]);
        P1v[c] = make_float4(p1[0], p1[1], p1[2], p1[3]);
    } else {
        int c = t - 128;
        float acc[3][4];
        #pragma unroll
        for (int gg = 0; gg < 3; ++gg)
            #pragma unroll
            for (int bb = 0; bb < 4; ++bb) acc[gg][bb] = 0.f;
        #pragma unroll 4
        for (int k = 0; k < 64; ++k) {
            float w0 = d_whht[k*192 + c];
            float w1 = d_whht[k*192 + 64 + c];
            float w2 = d_whht[k*192 + 128 + c];
            #pragma unroll
            for (int bb = 0; bb < 4; ++bb) {
                float hv = hold[bb][k];
                acc[0][bb] += w0*hv; acc[1][bb] += w1*hv; acc[2][bb] += w2*hv;
            }
        }
        float bh0 = bhh[c], bh1 = bhh[64+c], bh2 = bhh[128+c];
        #pragma unroll
        for (int bb = 0; bb < 4; ++bb) {
            ghs[bb][c]       = acc[0][bb] + bh0;
            ghs[bb][64+c]    = acc[1][bb] + bh1;
            ghs[bb][128+c]   = acc[2][bb] + bh2;
        }
        if (c < 8) {
            int bb = c >> 1, s = c & 1;
            float q = 0.f;
            #pragma unroll
            for (int i = 0; i < 48; ++i) q += a_s[bb][i][s];
            Qs[bb][s] = q;
        }
    }
    __syncthreads();

    // Phase C': gi[gc] = sum_c T0*P0 + T1*P1 + Q.v
    {
        int gc = t;
        const float2* Tp = d_T + (size_t)(sel*128)*192 + gc;
        float2 vv = __ldg(&d_v[sel*192 + gc]);
        float gi[4];
        #pragma unroll
        for (int bb = 0; bb < 4; ++bb)
            gi[bb] = Qs[bb][0]*vv.x + Qs[bb][1]*vv.y;
        #pragma unroll 4
        for (int c = 0; c < 128; ++c) {
            float2 tv = __ldg(&Tp[c*192]);
            float4 p0 = P0v[c], p1 = P1v[c];
            gi[0] += tv.x*p0.x + tv.y*p1.x;
            gi[1] += tv.x*p0.y + tv.y*p1.y;
            gi[2] += tv.x*p0.z + tv.y*p1.z;
            gi[3] += tv.x*p0.w + tv.y*p1.w;
        }
        #pragma unroll
        for (int bb = 0; bb < 4; ++bb) gis[bb][gc] = gi[bb];
    }
    __syncthreads();

    // combine (threads 0-63)
    if (t < 64) {
        int c = t;
        float bi0 = bih[c], bi1 = bih[64+c], bi2 = bih[128+c];
        #pragma unroll
        for (int bb = 0; bb < 4; ++bb) {
            int node = (b0+bb)*48 + j;
            float r = 1.f/(1.f+expf(-(gis[bb][c]      + bi0 + ghs[bb][c])));
            float z = 1.f/(1.f+expf(-(gis[bb][64+c]   + bi1 + ghs[bb][64+c])));
            float n = tanhf(gis[bb][128+c] + bi2 + r*ghs[bb][128+c]);
            float hn = (1.f-z)*n + z*hold[bb][c];
            h_out[node*64 + c] = d_mask[node]*hn;
        }
    }
}

// -------- readout: 4 nodes per CTA, float4 over rows --------
__global__ void __launch_bounds__(128) readout_kernel(
   const float* __restrict__ r0w0, const float* __restrict__ r0b0,
   const float* __restrict__ r0w1, const float* __restrict__ r0b1,
   const float* __restrict__ r0w2, const float* __restrict__ r0b2,
   const float* __restrict__ r1w0, const float* __restrict__ r1b0,
   const float* __restrict__ r1w1, const float* __restrict__ r1b1,
   const float* __restrict__ r1w2, const float* __restrict__ r1b2) {
    __shared__ float4 xinv[128];
    __shared__ float4 bufA[128];
    __shared__ float4 bufB[128];
    int c = threadIdx.x;
    int n0 = blockIdx.x * 4;
    {
        float v[4];
        #pragma unroll
        for (int r = 0; r < 4; ++r)
            v[r] = (c < 64) ? d_hf[(n0+r)*64 + c] : d_hA[(n0+r)*64 + (c-64)];
        xinv[c] = make_float4(v[0], v[1], v[2], v[3]);
    }
    __syncthreads();

    float4 acc;
    // Net0 L1 (128->128 relu)
    { float b = r0b0[c]; acc = make_float4(b,b,b,b); }
    #pragma unroll 4
    for (int k = 0; k < 128; ++k) {
        float w = __ldg(&r0w0[k*128+c]); float4 x = xinv[k];
        acc.x += x.x*w; acc.y += x.y*w; acc.z += x.z*w; acc.w += x.w*w;
    }
    bufA[c] = make_float4(fmaxf(acc.x,0.f), fmaxf(acc.y,0.f), fmaxf(acc.z,0.f), fmaxf(acc.w,0.f));
    __syncthreads();
    // Net0 L2
    { float b = r0b1[c]; acc = make_float4(b,b,b,b); }
    #pragma unroll 4
    for (int k = 0; k < 128; ++k) {
        float w = __ldg(&r0w1[k*128+c]); float4 x = bufA[k];
        acc.x += x.x*w; acc.y += x.y*w; acc.z += x.z*w; acc.w += x.w*w;
    }
    bufB[c] = make_float4(fmaxf(acc.x,0.f), fmaxf(acc.y,0.f), fmaxf(acc.z,0.f), fmaxf(acc.w,0.f));
    __syncthreads();
    // Net0 L3 (linear) -> out0 regs
    float4 out0;
    { float b = r0b2[c]; out0 = make_float4(b,b,b,b); }
    #pragma unroll 4
    for (int k = 0; k < 128; ++k) {
        float w = __ldg(&r0w2[k*128+c]); float4 x = bufB[k];
        out0.x += x.x*w; out0.y += x.y*w; out0.z += x.z*w; out0.w += x.w*w;
    }
    // Net1 L1 (64->128 relu) from hT half of xinv
    { float b = r1b0[c]; acc = make_float4(b,b,b,b); }
    #pragma unroll 4
    for (int k = 0; k < 64; ++k) {
        float w = __ldg(&r1w0[k*128+c]); float4 x = xinv[64+k];
        acc.x += x.x*w; acc.y += x.y*w; acc.z += x.z*w; acc.w += x.w*w;
    }
    bufA[c] = make_float4(fmaxf(acc.x,0.f), fmaxf(acc.y,0.f), fmaxf(acc.z,0.f), fmaxf(acc.w,0.f));
    __syncthreads();
    // Net1 L2
    { float b = r1b1[c]; acc = make_float4(b,b,b,b); }
    #pragma unroll 4
    for (int k = 0; k < 128; ++k) {
        float w = __ldg(&r1w1[k*128+c]); float4 x = bufA[k];
        acc.x += x.x*w; acc.y += x.y*w; acc.z += x.z*w; acc.w += x.w*w;
    }
    bufB[c] = make_float4(fmaxf(acc.x,0.f), fmaxf(acc.y,0.f), fmaxf(acc.z,0.f), fmaxf(acc.w,0.f));
    __syncthreads();
    // Net1 L3 (linear), multiply, mask, store
    float4 out1;
    { float b = r1b2[c]; out1 = make_float4(b,b,b,b); }
    #pragma unroll 4
    for (int k = 0; k < 128; ++k) {
        float w = __ldg(&r1w2[k*128+c]); float4 x = bufB[k];
        out1.x += x.x*w; out1.y += x.y*w; out1.z += x.z*w; out1.w += x.w*w;
    }
    d_tmp[(n0+0)*128 + c] = d_mask[n0+0]*out0.x*out1.x;
    d_tmp[(n0+1)*128 + c] = d_mask[n0+1]*out0.y*out1.y;
    d_tmp[(n0+2)*128 + c] = d_mask[n0+2]*out0.z*out1.z;
    d_tmp[(n0+3)*128 + c] = d_mask[n0+3]*out0.w*out1.w;
}

// -------- final node-sum + sigmoid --------
__global__ void reduce_kernel(float* __restrict__ out) {
    int b = blockIdx.x; int t = threadIdx.x;  // 128 threads
    float s = 0.f;
    #pragma unroll 4
    for (int j = 0; j < 48; ++j) s += d_tmp[(b*48+j)*128 + t];
    out[b*128+t] = 1.f/(1.f+expf(-s));
}

extern "C" void kernel_launch(void* const* d_in, const int* in_sizes, int n_in,
                              void* d_out, int out_size) {
    const float* g       = (const float*)d_in[0];
    const float* h0      = (const float*)d_in[1];
    const float* e       = (const float*)d_in[2];
    const float* msg_w0  = (const float*)d_in[3];
    const float* msg_b0  = (const float*)d_in[4];
    const float* msg_w1  = (const float*)d_in[5];
    const float* msg_b1  = (const float*)d_in[6];
    const float* msg_w2  = (const float*)d_in[7];
    const float* msg_b2  = (const float*)d_in[8];
    const float* gru_wih = (const float*)d_in[9];
    const float* gru_whh = (const float*)d_in[10];
    const float* gru_bih = (const float*)d_in[11];
    const float* gru_bhh = (const float*)d_in[12];
    const float* r0_w0   = (const float*)d_in[13];
    const float* r0_b0   = (const float*)d_in[14];
    const float* r0_w1   = (const float*)d_in[15];
    const float* r0_b1   = (const float*)d_in[16];
    const float* r0_w2   = (const float*)d_in[17];
    const float* r0_b2   = (const float*)d_in[18];
    const float* r1_w0   = (const float*)d_in[19];
    const float* r1_b0   = (const float*)d_in[20];
    const float* r1_w1   = (const float*)d_in[21];
    const float* r1_b1   = (const float*)d_in[22];
    const float* r1_w2   = (const float*)d_in[23];
    const float* r1_b2   = (const float*)d_in[24];
    float* out = (float*)d_out;

    cudaFuncSetAttribute(relu2_kernel, cudaFuncAttributeMaxDynamicSharedMemorySize, RELU2_SMEM);

    prep_kernel<<<128, 64>>>(msg_w2, msg_b2);
    prep_T_kernel<<<384, 192>>>(gru_wih);
    prep_v_kernel<<<3, 192>>>(gru_wih);
    prep_gru_kernel<<<64, 192>>>(gru_whh);
    prep_w1t_kernel<<<64, 256>>>(msg_w1);
    prep_w0t_kernel<<<8, 256>>>(msg_w0);
    init_kernel<<<NNODE, 64>>>(h0);
    relu2_kernel<<<NE/128, 256, RELU2_SMEM>>>(e, msg_b0, msg_b1);
    // L1: hf -> hA ; L2: hA -> hB ; L3: hB -> hA
    layer_kernel<<<dim3(48, 4), 192>>>(0, 1, g, gru_bih, gru_bhh);
    layer_kernel<<<dim3(48, 4), 192>>>(1, 2, g, gru_bih, gru_bhh);
    layer_kernel<<<dim3(48, 4), 192>>>(2, 1, g, gru_bih, gru_bhh);
    readout_kernel<<<NNODE/4, 128>>>(r0_w0, r0_b0, r0_w1, r0_b1, r0_w2, r0_b2,
                                     r1_w0, r1_b0, r1_w1, r1_b1, r1_w2, r1_b2);
    reduce_kernel<<<NB, 128>>>(out);
}